// round 6
// baseline (speedup 1.0000x reference)
#include <cuda_runtime.h>
#include <cuda_fp16.h>
#include <mma.h>
#include <math.h>
#include <stdint.h>

using namespace nvcuda;

#define N_MAX 100000
#define E_MAX 1600000

// ---------------- device scratch (static, no allocation) ----------------
__device__ int    g_deg[N_MAX];
__device__ int    g_cursor[N_MAX];
__device__ int    g_rowstart[N_MAX];
__device__ int    g_total;
__device__ int    g_ebuf[E_MAX];
__device__ __align__(16) __half g_y1h[N_MAX * 64]; // fp16(x @ W_l1)
__device__ __align__(16) float  g_r1[N_MAX * 64];  // x @ W_r1 + b_l1
__device__ __align__(16) __half g_y2h[N_MAX * 40]; // fp16(hid @ W_l2)
__device__ __align__(16) float  g_r2[N_MAX * 40];  // hid @ W_r2 + b_l2

// ---------------- CSR build (order-free segments) ----------------
__global__ void zero_kernel(int n) {
    int i = blockIdx.x * blockDim.x + threadIdx.x;
    if (i < n) { g_deg[i] = 0; g_cursor[i] = 0; }
    if (i == 0) g_total = 0;
}

__global__ void count_deg_kernel(const int* __restrict__ dst, int e) {
    int i = blockIdx.x * blockDim.x + threadIdx.x;
    if (i < e) atomicAdd(&g_deg[dst[i]], 1);
}

// per-node segment base via block-aggregated atomic (order-free CSR)
__global__ void assign_kernel(int n) {
    __shared__ int wsum[32];
    __shared__ int blockbase;
    int t = threadIdx.x;
    int i = blockIdx.x * blockDim.x + t;
    int v = (i < n) ? g_deg[i] : 0;
    int x = v;
#pragma unroll
    for (int o = 1; o < 32; o <<= 1) {
        int u = __shfl_up_sync(0xffffffffu, x, o);
        if ((t & 31) >= o) x += u;
    }
    if ((t & 31) == 31) wsum[t >> 5] = x;
    __syncthreads();
    if (t < 32) {
        int w = (t < 8) ? wsum[t] : 0;   // 256 threads -> 8 warps
#pragma unroll
        for (int o = 1; o < 8; o <<= 1) {
            int u = __shfl_up_sync(0xffffffffu, w, o);
            if (t >= o) w += u;
        }
        if (t == 7) blockbase = atomicAdd(&g_total, w);
        wsum[t] = w;
    }
    __syncthreads();
    int base = blockbase + ((t >= 32) ? wsum[(t >> 5) - 1] : 0);
    if (i < n) g_rowstart[i] = base + x - v;
}

__global__ void fill_csr_kernel(const int* __restrict__ src,
                                const int* __restrict__ dst, int e) {
    int i = blockIdx.x * blockDim.x + threadIdx.x;
    if (i < e) {
        int d = dst[i];
        int pos = atomicAdd(&g_cursor[d], 1);
        g_ebuf[g_rowstart[d] + pos] = src[i];
    }
}

// ---------------- layer-1 HMMA GEMM: C[128,128] = x_tile @ [Wl1|Wr1] ----
#define LDA1 136
__global__ __launch_bounds__(256) void gemm1_kernel(
    const float* __restrict__ x, const float* __restrict__ Wl,
    const float* __restrict__ Wr, const float* __restrict__ bl, int n) {
    extern __shared__ char smem[];
    __half* As = (__half*)smem;
    __half* Bs = (__half*)(smem + 128 * LDA1 * 2);
    float*  Cs = (float*)smem;
    int tid = threadIdx.x;
    int node0 = blockIdx.x * 128;

    for (int i = tid; i < 128 * 32; i += 256) {
        int row = i >> 5, c4 = i & 31;
        int gr = node0 + row;
        float4 v = (gr < n) ? ((const float4*)x)[gr * 32 + c4]
                            : make_float4(0.f, 0.f, 0.f, 0.f);
        *(__half2*)&As[row * LDA1 + c4 * 4] = __floats2half2_rn(v.x, v.y);
        *(__half2*)&As[row * LDA1 + c4 * 4 + 2] = __floats2half2_rn(v.z, v.w);
    }
    for (int i = tid; i < 128 * 64; i += 256) {
        int k = i >> 6, c = i & 63;
        Bs[k * LDA1 + c] = __float2half_rn(Wl[k * 64 + c]);
        Bs[k * LDA1 + 64 + c] = __float2half_rn(Wr[k * 64 + c]);
    }
    __syncthreads();

    int wid = tid >> 5;
    int wr = (wid >> 1) * 32;
    int wc = (wid & 1) * 64;
    wmma::fragment<wmma::accumulator, 16, 16, 16, float> acc[2][4];
#pragma unroll
    for (int i = 0; i < 2; i++)
#pragma unroll
        for (int j = 0; j < 4; j++) wmma::fill_fragment(acc[i][j], 0.f);

#pragma unroll
    for (int k = 0; k < 128; k += 16) {
        wmma::fragment<wmma::matrix_a, 16, 16, 16, __half, wmma::row_major> af[2];
        wmma::fragment<wmma::matrix_b, 16, 16, 16, __half, wmma::row_major> bf[4];
        wmma::load_matrix_sync(af[0], &As[wr * LDA1 + k], LDA1);
        wmma::load_matrix_sync(af[1], &As[(wr + 16) * LDA1 + k], LDA1);
#pragma unroll
        for (int j = 0; j < 4; j++)
            wmma::load_matrix_sync(bf[j], &Bs[k * LDA1 + wc + j * 16], LDA1);
#pragma unroll
        for (int i = 0; i < 2; i++)
#pragma unroll
            for (int j = 0; j < 4; j++)
                wmma::mma_sync(acc[i][j], af[i], bf[j], acc[i][j]);
    }
    __syncthreads();
#pragma unroll
    for (int i = 0; i < 2; i++)
#pragma unroll
        for (int j = 0; j < 4; j++)
            wmma::store_matrix_sync(&Cs[(wr + i * 16) * LDA1 + wc + j * 16],
                                    acc[i][j], LDA1, wmma::mem_row_major);
    __syncthreads();

    int row = tid >> 1, half = tid & 1;
    int m = node0 + row;
    if (m < n) {
        if (half == 0) {
            uint32_t* dst = (uint32_t*)&g_y1h[m * 64];
            const float* c = &Cs[row * LDA1];
#pragma unroll
            for (int j = 0; j < 64; j += 2) {
                __half2 h = __floats2half2_rn(c[j], c[j + 1]);
                dst[j >> 1] = *reinterpret_cast<uint32_t*>(&h);
            }
        } else {
            float4* dst = (float4*)&g_r1[m * 64];
            const float* c = &Cs[row * LDA1 + 64];
#pragma unroll
            for (int j = 0; j < 64; j += 4)
                dst[j >> 2] = make_float4(c[j] + bl[j], c[j + 1] + bl[j + 1],
                                          c[j + 2] + bl[j + 2], c[j + 3] + bl[j + 3]);
        }
    }
}

// ------- fused: hid = relu(gather_mean(y1)+r1); [y2h|r2] = hid @ [Wl2|Wr2] ---
// block = 256 threads / 8 warps, 128 nodes; warp w gathers rows w*16..w*16+15
#define LDA2 72
#define LDB2 88
__global__ __launch_bounds__(256) void combine1_gemm2_kernel(
    const float* __restrict__ Wl, const float* __restrict__ Wr,
    const float* __restrict__ bl, int n) {
    extern __shared__ char smem[];
    __half* As = (__half*)smem;                       // [128][72] hid tile
    __half* Bs = (__half*)(smem + 128 * LDA2 * 2);    // [64][88]
    float*  Cs = (float*)smem;                        // reuse: [128][88]
    int tid = threadIdx.x;
    int wid = tid >> 5, lane = tid & 31;
    int node0 = blockIdx.x * 128;

    // B: [k][0..39] = Wl2, [k][40..79] = Wr2
    for (int i = tid; i < 64 * 40; i += 256) {
        int k = i / 40, c = i % 40;
        Bs[k * LDB2 + c] = __float2half_rn(Wl[k * 40 + c]);
        Bs[k * LDB2 + 40 + c] = __float2half_rn(Wr[k * 40 + c]);
    }

    // gather+relu: each warp produces 16 rows of the hid tile
    const __half2* y1 = (const __half2*)g_y1h;
    for (int r = 0; r < 16; r++) {
        int row = wid * 16 + r;
        int node = node0 + row;
        float a0 = 0.f, a1 = 0.f, b0 = 0.f, b1 = 0.f;
        float c0 = 0.f, c1 = 0.f, d0 = 0.f, d1 = 0.f;
        float h0 = 0.f, h1 = 0.f;
        if (node < n) {
            int s = g_rowstart[node];
            int dg = g_deg[node];
            int e = s + dg;
            float inv = 1.f / (float)max(dg, 1);
            for (int base = s; base < e; base += 32) {
                int cnt = min(32, e - base);
                int idx = (lane < cnt) ? g_ebuf[base + lane] : 0;
                int j = 0;
                for (; j + 4 <= cnt; j += 4) {
                    int n0 = __shfl_sync(0xffffffffu, idx, j);
                    int n1 = __shfl_sync(0xffffffffu, idx, j + 1);
                    int n2 = __shfl_sync(0xffffffffu, idx, j + 2);
                    int n3 = __shfl_sync(0xffffffffu, idx, j + 3);
                    float2 v0 = __half22float2(y1[n0 * 32 + lane]);
                    float2 v1 = __half22float2(y1[n1 * 32 + lane]);
                    float2 v2 = __half22float2(y1[n2 * 32 + lane]);
                    float2 v3 = __half22float2(y1[n3 * 32 + lane]);
                    a0 += v0.x; a1 += v0.y;
                    b0 += v1.x; b1 += v1.y;
                    c0 += v2.x; c1 += v2.y;
                    d0 += v3.x; d1 += v3.y;
                }
                for (; j < cnt; j++) {
                    int n0 = __shfl_sync(0xffffffffu, idx, j);
                    float2 v0 = __half22float2(y1[n0 * 32 + lane]);
                    a0 += v0.x; a1 += v0.y;
                }
            }
            a0 += b0 + c0 + d0;
            a1 += b1 + c1 + d1;
            float2 rr = *(const float2*)&g_r1[node * 64 + lane * 2];
            h0 = fmaxf(a0 * inv + rr.x, 0.f);
            h1 = fmaxf(a1 * inv + rr.y, 0.f);
        }
        *(__half2*)&As[row * LDA2 + lane * 2] = __floats2half2_rn(h0, h1);
    }
    __syncthreads();

    // wmma: C[128,80] = As @ Bs
    int wr = wid * 16;
    wmma::fragment<wmma::accumulator, 16, 16, 16, float> acc[5];
#pragma unroll
    for (int j = 0; j < 5; j++) wmma::fill_fragment(acc[j], 0.f);
#pragma unroll
    for (int k = 0; k < 64; k += 16) {
        wmma::fragment<wmma::matrix_a, 16, 16, 16, __half, wmma::row_major> af;
        wmma::fragment<wmma::matrix_b, 16, 16, 16, __half, wmma::row_major> bf[5];
        wmma::load_matrix_sync(af, &As[wr * LDA2 + k], LDA2);
#pragma unroll
        for (int j = 0; j < 5; j++)
            wmma::load_matrix_sync(bf[j], &Bs[k * LDB2 + j * 16], LDB2);
#pragma unroll
        for (int j = 0; j < 5; j++) wmma::mma_sync(acc[j], af, bf[j], acc[j]);
    }
    __syncthreads();
#pragma unroll
    for (int j = 0; j < 5; j++)
        wmma::store_matrix_sync(&Cs[wr * LDB2 + j * 16], acc[j], LDB2,
                                wmma::mem_row_major);
    __syncthreads();

    int row = tid >> 1, half = tid & 1;
    int m = node0 + row;
    if (m < n) {
        if (half == 0) {
            uint32_t* dst = (uint32_t*)&g_y2h[m * 40];
            const float* c = &Cs[row * LDB2];
#pragma unroll
            for (int j = 0; j < 40; j += 2) {
                __half2 h = __floats2half2_rn(c[j], c[j + 1]);
                dst[j >> 1] = *reinterpret_cast<uint32_t*>(&h);
            }
        } else {
            float4* dst = (float4*)&g_r2[m * 40];
            const float* c = &Cs[row * LDB2 + 40];
#pragma unroll
            for (int j = 0; j < 40; j += 4)
                dst[j >> 2] = make_float4(c[j] + bl[j], c[j + 1] + bl[j + 1],
                                          c[j + 2] + bl[j + 2], c[j + 3] + bl[j + 3]);
        }
    }
}

// ------- combine layer 2: out = log_softmax(gather_mean(y2) + r2) -------
__global__ void combine2_kernel(float* __restrict__ out, int n) {
    int node = (blockIdx.x * blockDim.x + threadIdx.x) >> 5;
    int lane = threadIdx.x & 31;
    if (node >= n) return;
    int s = g_rowstart[node];
    int dg = g_deg[node];
    int e = s + dg;
    float inv = 1.f / (float)max(dg, 1);
    const __half2* y2 = (const __half2*)g_y2h;
    bool act = lane < 20;
    float a0 = 0.f, a1 = 0.f, b0 = 0.f, b1 = 0.f;
    float c0 = 0.f, c1 = 0.f, d0 = 0.f, d1 = 0.f;
    for (int base = s; base < e; base += 32) {
        int cnt = min(32, e - base);
        int idx = (lane < cnt) ? g_ebuf[base + lane] : 0;
        int j = 0;
        for (; j + 4 <= cnt; j += 4) {
            int n0 = __shfl_sync(0xffffffffu, idx, j);
            int n1 = __shfl_sync(0xffffffffu, idx, j + 1);
            int n2 = __shfl_sync(0xffffffffu, idx, j + 2);
            int n3 = __shfl_sync(0xffffffffu, idx, j + 3);
            if (act) {
                float2 v0 = __half22float2(y2[n0 * 20 + lane]);
                float2 v1 = __half22float2(y2[n1 * 20 + lane]);
                float2 v2 = __half22float2(y2[n2 * 20 + lane]);
                float2 v3 = __half22float2(y2[n3 * 20 + lane]);
                a0 += v0.x; a1 += v0.y;
                b0 += v1.x; b1 += v1.y;
                c0 += v2.x; c1 += v2.y;
                d0 += v3.x; d1 += v3.y;
            }
        }
        for (; j < cnt; j++) {
            int n0 = __shfl_sync(0xffffffffu, idx, j);
            if (act) {
                float2 v0 = __half22float2(y2[n0 * 20 + lane]);
                a0 += v0.x; a1 += v0.y;
            }
        }
    }
    a0 += b0 + c0 + d0;
    a1 += b1 + c1 + d1;
    const float NEG_INF = __int_as_float(0xff800000);
    float v0 = NEG_INF, v1 = NEG_INF;
    if (act) {
        v0 = a0 * inv + g_r2[node * 40 + 2 * lane];
        v1 = a1 * inv + g_r2[node * 40 + 2 * lane + 1];
    }
    float m = fmaxf(v0, v1);
#pragma unroll
    for (int o = 16; o > 0; o >>= 1) m = fmaxf(m, __shfl_xor_sync(0xffffffffu, m, o));
    float sum = act ? (expf(v0 - m) + expf(v1 - m)) : 0.f;
#pragma unroll
    for (int o = 16; o > 0; o >>= 1) sum += __shfl_xor_sync(0xffffffffu, sum, o);
    float lse = logf(sum);
    if (act) {
        out[node * 40 + 2 * lane] = v0 - m - lse;
        out[node * 40 + 2 * lane + 1] = v1 - m - lse;
    }
}

// ---------------- launch ----------------
extern "C" void kernel_launch(void* const* d_in, const int* in_sizes, int n_in,
                              void* d_out, int out_size) {
    const float* x   = (const float*)d_in[0];
    const int*   ei  = (const int*)d_in[1];   // int64 inputs delivered as int32
    const float* Wl1 = (const float*)d_in[2];
    const float* bl1 = (const float*)d_in[3];
    const float* Wr1 = (const float*)d_in[4];
    const float* Wl2 = (const float*)d_in[5];
    const float* bl2 = (const float*)d_in[6];
    const float* Wr2 = (const float*)d_in[7];
    float* out = (float*)d_out;

    int n = in_sizes[0] / 128;
    int e = in_sizes[1] / 2;
    const int* src = ei;
    const int* dst = ei + e;

    const int SMEM1 = 128 * LDA1 * 2 * 2;   // 69632 B
    const int SMEMF = 128 * LDB2 * 4;       // 45056 B (C view is the max)
    cudaFuncSetAttribute(gemm1_kernel, cudaFuncAttributeMaxDynamicSharedMemorySize, SMEM1);
    cudaFuncSetAttribute(combine1_gemm2_kernel, cudaFuncAttributeMaxDynamicSharedMemorySize, SMEMF);

    cudaStream_t s2;
    cudaStreamCreateWithFlags(&s2, cudaStreamNonBlocking);
    cudaEvent_t evFork, evJoin;
    cudaEventCreateWithFlags(&evFork, cudaEventDisableTiming);
    cudaEventCreateWithFlags(&evJoin, cudaEventDisableTiming);

    cudaEventRecord(evFork, 0);
    cudaStreamWaitEvent(s2, evFork, 0);

    // CSR chain (side stream): zero, count, assign, fill
    zero_kernel<<<(n + 255) / 256, 256, 0, s2>>>(n);
    count_deg_kernel<<<(e + 255) / 256, 256, 0, s2>>>(dst, e);
    assign_kernel<<<(n + 255) / 256, 256, 0, s2>>>(n);
    fill_csr_kernel<<<(e + 255) / 256, 256, 0, s2>>>(src, dst, e);
    cudaEventRecord(evJoin, s2);

    int nblk = (n + 127) / 128;
    gemm1_kernel<<<nblk, 256, SMEM1>>>(x, Wl1, Wr1, bl1, n);

    cudaStreamWaitEvent(0, evJoin, 0);
    combine1_gemm2_kernel<<<nblk, 256, SMEMF>>>(Wl2, Wr2, bl2, n);
    combine2_kernel<<<(n * 32 + 255) / 256, 256>>>(out, n);
}

// round 7
// speedup vs baseline: 1.1550x; 1.1550x over previous
#include <cuda_runtime.h>
#include <cuda_fp16.h>
#include <mma.h>
#include <math.h>
#include <stdint.h>

using namespace nvcuda;

#define N_MAX 100000
#define E_MAX 1600000

// ---------------- device scratch (static, no allocation) ----------------
__device__ int    g_deg[N_MAX];
__device__ int    g_cursor[N_MAX];     // initialized to rowstart by assign_kernel
__device__ int    g_rowstart[N_MAX];
__device__ int    g_total;
__device__ int    g_ebuf[E_MAX];
__device__ __align__(16) __half g_y1h[N_MAX * 64]; // fp16(x @ W_l1)
__device__ __align__(16) float  g_r1[N_MAX * 64];  // x @ W_r1 + b_l1
__device__ __align__(16) __half g_hid[N_MAX * 64]; // fp16(relu(mean + root))
__device__ __align__(16) __half g_y2h[N_MAX * 40]; // fp16(hid @ W_l2)
__device__ __align__(16) float  g_r2[N_MAX * 40];  // hid @ W_r2 + b_l2

// ---------------- CSR build (order-free segments) ----------------
__global__ void count_deg_kernel(const int* __restrict__ dst, int e) {
    int i = blockIdx.x * blockDim.x + threadIdx.x;
    if (i < e) atomicAdd(&g_deg[dst[i]], 1);
}

// per-node segment base via block-aggregated atomic; cursor := rowstart
__global__ void assign_kernel(int n) {
    __shared__ int wsum[32];
    __shared__ int blockbase;
    int t = threadIdx.x;
    int i = blockIdx.x * blockDim.x + t;
    int v = (i < n) ? g_deg[i] : 0;
    int x = v;
#pragma unroll
    for (int o = 1; o < 32; o <<= 1) {
        int u = __shfl_up_sync(0xffffffffu, x, o);
        if ((t & 31) >= o) x += u;
    }
    if ((t & 31) == 31) wsum[t >> 5] = x;
    __syncthreads();
    if (t < 32) {
        int w = (t < 8) ? wsum[t] : 0;   // 256 threads -> 8 warps
#pragma unroll
        for (int o = 1; o < 8; o <<= 1) {
            int u = __shfl_up_sync(0xffffffffu, w, o);
            if (t >= o) w += u;
        }
        if (t == 7) blockbase = atomicAdd(&g_total, w);
        wsum[t] = w;
    }
    __syncthreads();
    int base = blockbase + ((t >= 32) ? wsum[(t >> 5) - 1] : 0);
    if (i < n) {
        int rs = base + x - v;
        g_rowstart[i] = rs;
        g_cursor[i] = rs;
    }
}

__global__ void fill_csr_kernel(const int* __restrict__ src,
                                const int* __restrict__ dst, int e) {
    int i = blockIdx.x * blockDim.x + threadIdx.x;
    if (i < e) {
        int pos = atomicAdd(&g_cursor[dst[i]], 1);  // absolute slot
        g_ebuf[pos] = src[i];
    }
}

// ---------------- layer-1 HMMA GEMM: C[128,128] = x_tile @ [Wl1|Wr1] ----
#define LDA1 136
__global__ __launch_bounds__(256) void gemm1_kernel(
    const float* __restrict__ x, const float* __restrict__ Wl,
    const float* __restrict__ Wr, const float* __restrict__ bl, int n) {
    extern __shared__ char smem[];
    __half* As = (__half*)smem;
    __half* Bs = (__half*)(smem + 128 * LDA1 * 2);
    float*  Cs = (float*)smem;
    int tid = threadIdx.x;
    int node0 = blockIdx.x * 128;

    for (int i = tid; i < 128 * 32; i += 256) {
        int row = i >> 5, c4 = i & 31;
        int gr = node0 + row;
        float4 v = (gr < n) ? ((const float4*)x)[gr * 32 + c4]
                            : make_float4(0.f, 0.f, 0.f, 0.f);
        *(__half2*)&As[row * LDA1 + c4 * 4] = __floats2half2_rn(v.x, v.y);
        *(__half2*)&As[row * LDA1 + c4 * 4 + 2] = __floats2half2_rn(v.z, v.w);
    }
    for (int i = tid; i < 128 * 64; i += 256) {
        int k = i >> 6, c = i & 63;
        Bs[k * LDA1 + c] = __float2half_rn(Wl[k * 64 + c]);
        Bs[k * LDA1 + 64 + c] = __float2half_rn(Wr[k * 64 + c]);
    }
    __syncthreads();

    int wid = tid >> 5;
    int wr = (wid >> 1) * 32;
    int wc = (wid & 1) * 64;
    wmma::fragment<wmma::accumulator, 16, 16, 16, float> acc[2][4];
#pragma unroll
    for (int i = 0; i < 2; i++)
#pragma unroll
        for (int j = 0; j < 4; j++) wmma::fill_fragment(acc[i][j], 0.f);

#pragma unroll
    for (int k = 0; k < 128; k += 16) {
        wmma::fragment<wmma::matrix_a, 16, 16, 16, __half, wmma::row_major> af[2];
        wmma::fragment<wmma::matrix_b, 16, 16, 16, __half, wmma::row_major> bf[4];
        wmma::load_matrix_sync(af[0], &As[wr * LDA1 + k], LDA1);
        wmma::load_matrix_sync(af[1], &As[(wr + 16) * LDA1 + k], LDA1);
#pragma unroll
        for (int j = 0; j < 4; j++)
            wmma::load_matrix_sync(bf[j], &Bs[k * LDA1 + wc + j * 16], LDA1);
#pragma unroll
        for (int i = 0; i < 2; i++)
#pragma unroll
            for (int j = 0; j < 4; j++)
                wmma::mma_sync(acc[i][j], af[i], bf[j], acc[i][j]);
    }
    __syncthreads();
#pragma unroll
    for (int i = 0; i < 2; i++)
#pragma unroll
        for (int j = 0; j < 4; j++)
            wmma::store_matrix_sync(&Cs[(wr + i * 16) * LDA1 + wc + j * 16],
                                    acc[i][j], LDA1, wmma::mem_row_major);
    __syncthreads();

    int row = tid >> 1, half = tid & 1;
    int m = node0 + row;
    if (m < n) {
        if (half == 0) {
            uint32_t* dst = (uint32_t*)&g_y1h[m * 64];
            const float* c = &Cs[row * LDA1];
#pragma unroll
            for (int j = 0; j < 64; j += 2) {
                __half2 h = __floats2half2_rn(c[j], c[j + 1]);
                dst[j >> 1] = *reinterpret_cast<uint32_t*>(&h);
            }
        } else {
            float4* dst = (float4*)&g_r1[m * 64];
            const float* c = &Cs[row * LDA1 + 64];
#pragma unroll
            for (int j = 0; j < 64; j += 4)
                dst[j >> 2] = make_float4(c[j] + bl[j], c[j + 1] + bl[j + 1],
                                          c[j + 2] + bl[j + 2], c[j + 3] + bl[j + 3]);
        }
    }
}

// ------- combine layer 1: hid = fp16(relu(gather_mean(y1) + r1)) --------
__global__ void combine1_kernel(int n) {
    int node = (blockIdx.x * blockDim.x + threadIdx.x) >> 5;
    int lane = threadIdx.x & 31;
    if (node >= n) return;
    int s = g_rowstart[node];
    int dg = g_deg[node];
    int e = s + dg;
    float inv = 1.f / (float)max(dg, 1);
    const __half2* y1 = (const __half2*)g_y1h;
    float a0 = 0.f, a1 = 0.f, b0 = 0.f, b1 = 0.f;
    float c0 = 0.f, c1 = 0.f, d0 = 0.f, d1 = 0.f;
    for (int base = s; base < e; base += 32) {
        int cnt = min(32, e - base);
        int idx = (lane < cnt) ? g_ebuf[base + lane] : 0;
        int j = 0;
        for (; j + 4 <= cnt; j += 4) {
            int n0 = __shfl_sync(0xffffffffu, idx, j);
            int n1 = __shfl_sync(0xffffffffu, idx, j + 1);
            int n2 = __shfl_sync(0xffffffffu, idx, j + 2);
            int n3 = __shfl_sync(0xffffffffu, idx, j + 3);
            float2 v0 = __half22float2(y1[n0 * 32 + lane]);
            float2 v1 = __half22float2(y1[n1 * 32 + lane]);
            float2 v2 = __half22float2(y1[n2 * 32 + lane]);
            float2 v3 = __half22float2(y1[n3 * 32 + lane]);
            a0 += v0.x; a1 += v0.y;
            b0 += v1.x; b1 += v1.y;
            c0 += v2.x; c1 += v2.y;
            d0 += v3.x; d1 += v3.y;
        }
        for (; j < cnt; j++) {
            int n0 = __shfl_sync(0xffffffffu, idx, j);
            float2 v0 = __half22float2(y1[n0 * 32 + lane]);
            a0 += v0.x; a1 += v0.y;
        }
    }
    a0 += b0 + c0 + d0;
    a1 += b1 + c1 + d1;
    float2 r = *(const float2*)&g_r1[node * 64 + lane * 2];
    float h0 = fmaxf(a0 * inv + r.x, 0.f);
    float h1 = fmaxf(a1 * inv + r.y, 0.f);
    *(__half2*)&g_hid[node * 64 + lane * 2] = __floats2half2_rn(h0, h1);
}

// ---------------- layer-2 HMMA GEMM: C[128,80] = hid_tile @ [Wl2|Wr2] ---
#define LDA2 72
#define LDB2 88
__global__ __launch_bounds__(256) void gemm2_kernel(
    const float* __restrict__ Wl, const float* __restrict__ Wr,
    const float* __restrict__ bl, int n) {
    extern __shared__ char smem[];
    __half* As = (__half*)smem;                       // [128][72]
    __half* Bs = (__half*)(smem + 128 * LDA2 * 2);    // [64][88]
    float*  Cs = (float*)smem;                        // reuse: [128][88]
    int tid = threadIdx.x;
    int node0 = blockIdx.x * 128;

    for (int i = tid; i < 128 * 8; i += 256) {
        int row = i >> 3, c8 = i & 7;
        int gr = node0 + row;
        uint4 v = (gr < n) ? ((const uint4*)g_hid)[gr * 8 + c8] : make_uint4(0, 0, 0, 0);
        *(uint4*)&As[row * LDA2 + c8 * 8] = v;
    }
    for (int i = tid; i < 64 * 40; i += 256) {
        int k = i / 40, c = i % 40;
        Bs[k * LDB2 + c] = __float2half_rn(Wl[k * 40 + c]);
        Bs[k * LDB2 + 40 + c] = __float2half_rn(Wr[k * 40 + c]);
    }
    __syncthreads();

    int wid = tid >> 5;
    int wr = wid * 16;
    wmma::fragment<wmma::accumulator, 16, 16, 16, float> acc[5];
#pragma unroll
    for (int j = 0; j < 5; j++) wmma::fill_fragment(acc[j], 0.f);
#pragma unroll
    for (int k = 0; k < 64; k += 16) {
        wmma::fragment<wmma::matrix_a, 16, 16, 16, __half, wmma::row_major> af;
        wmma::fragment<wmma::matrix_b, 16, 16, 16, __half, wmma::row_major> bf[5];
        wmma::load_matrix_sync(af, &As[wr * LDA2 + k], LDA2);
#pragma unroll
        for (int j = 0; j < 5; j++)
            wmma::load_matrix_sync(bf[j], &Bs[k * LDB2 + j * 16], LDB2);
#pragma unroll
        for (int j = 0; j < 5; j++) wmma::mma_sync(acc[j], af, bf[j], acc[j]);
    }
    __syncthreads();
#pragma unroll
    for (int j = 0; j < 5; j++)
        wmma::store_matrix_sync(&Cs[wr * LDB2 + j * 16], acc[j], LDB2,
                                wmma::mem_row_major);
    __syncthreads();

    int row = tid >> 1, half = tid & 1;
    int m = node0 + row;
    if (m < n) {
        if (half == 0) {
            uint32_t* dst = (uint32_t*)&g_y2h[m * 40];
            const float* c = &Cs[row * LDB2];
#pragma unroll
            for (int j = 0; j < 40; j += 2) {
                __half2 h = __floats2half2_rn(c[j], c[j + 1]);
                dst[j >> 1] = *reinterpret_cast<uint32_t*>(&h);
            }
        } else {
            float4* dst = (float4*)&g_r2[m * 40];
            const float* c = &Cs[row * LDB2 + 40];
#pragma unroll
            for (int j = 0; j < 40; j += 4)
                dst[j >> 2] = make_float4(c[j] + bl[j], c[j + 1] + bl[j + 1],
                                          c[j + 2] + bl[j + 2], c[j + 3] + bl[j + 3]);
        }
    }
}

// ------- combine layer 2: out = log_softmax(gather_mean(y2) + r2) -------
__global__ void combine2_kernel(float* __restrict__ out, int n) {
    int node = (blockIdx.x * blockDim.x + threadIdx.x) >> 5;
    int lane = threadIdx.x & 31;
    if (node >= n) return;
    int s = g_rowstart[node];
    int dg = g_deg[node];
    int e = s + dg;
    float inv = 1.f / (float)max(dg, 1);
    const __half2* y2 = (const __half2*)g_y2h;
    bool act = lane < 20;
    float a0 = 0.f, a1 = 0.f, b0 = 0.f, b1 = 0.f;
    float c0 = 0.f, c1 = 0.f, d0 = 0.f, d1 = 0.f;
    for (int base = s; base < e; base += 32) {
        int cnt = min(32, e - base);
        int idx = (lane < cnt) ? g_ebuf[base + lane] : 0;
        int j = 0;
        for (; j + 4 <= cnt; j += 4) {
            int n0 = __shfl_sync(0xffffffffu, idx, j);
            int n1 = __shfl_sync(0xffffffffu, idx, j + 1);
            int n2 = __shfl_sync(0xffffffffu, idx, j + 2);
            int n3 = __shfl_sync(0xffffffffu, idx, j + 3);
            if (act) {
                float2 v0 = __half22float2(y2[n0 * 20 + lane]);
                float2 v1 = __half22float2(y2[n1 * 20 + lane]);
                float2 v2 = __half22float2(y2[n2 * 20 + lane]);
                float2 v3 = __half22float2(y2[n3 * 20 + lane]);
                a0 += v0.x; a1 += v0.y;
                b0 += v1.x; b1 += v1.y;
                c0 += v2.x; c1 += v2.y;
                d0 += v3.x; d1 += v3.y;
            }
        }
        for (; j < cnt; j++) {
            int n0 = __shfl_sync(0xffffffffu, idx, j);
            if (act) {
                float2 v0 = __half22float2(y2[n0 * 20 + lane]);
                a0 += v0.x; a1 += v0.y;
            }
        }
    }
    a0 += b0 + c0 + d0;
    a1 += b1 + c1 + d1;
    const float NEG_INF = __int_as_float(0xff800000);
    float v0 = NEG_INF, v1 = NEG_INF;
    if (act) {
        v0 = a0 * inv + g_r2[node * 40 + 2 * lane];
        v1 = a1 * inv + g_r2[node * 40 + 2 * lane + 1];
    }
    float m = fmaxf(v0, v1);
#pragma unroll
    for (int o = 16; o > 0; o >>= 1) m = fmaxf(m, __shfl_xor_sync(0xffffffffu, m, o));
    float sum = act ? (expf(v0 - m) + expf(v1 - m)) : 0.f;
#pragma unroll
    for (int o = 16; o > 0; o >>= 1) sum += __shfl_xor_sync(0xffffffffu, sum, o);
    float lse = logf(sum);
    if (act) {
        out[node * 40 + 2 * lane] = v0 - m - lse;
        out[node * 40 + 2 * lane + 1] = v1 - m - lse;
    }
}

// ---------------- launch ----------------
extern "C" void kernel_launch(void* const* d_in, const int* in_sizes, int n_in,
                              void* d_out, int out_size) {
    const float* x   = (const float*)d_in[0];
    const int*   ei  = (const int*)d_in[1];   // int64 inputs delivered as int32
    const float* Wl1 = (const float*)d_in[2];
    const float* bl1 = (const float*)d_in[3];
    const float* Wr1 = (const float*)d_in[4];
    const float* Wl2 = (const float*)d_in[5];
    const float* bl2 = (const float*)d_in[6];
    const float* Wr2 = (const float*)d_in[7];
    float* out = (float*)d_out;

    int n = in_sizes[0] / 128;
    int e = in_sizes[1] / 2;
    const int* src = ei;
    const int* dst = ei + e;

    const int SMEM1 = 128 * LDA1 * 2 * 2;   // 69632 B
    const int SMEM2 = 128 * LDB2 * 4;       // 45056 B
    cudaFuncSetAttribute(gemm1_kernel, cudaFuncAttributeMaxDynamicSharedMemorySize, SMEM1);
    cudaFuncSetAttribute(gemm2_kernel, cudaFuncAttributeMaxDynamicSharedMemorySize, SMEM2);

    void* deg_ptr = nullptr;
    void* total_ptr = nullptr;
    cudaGetSymbolAddress(&deg_ptr, g_deg);
    cudaGetSymbolAddress(&total_ptr, g_total);

    cudaStream_t s2;
    cudaStreamCreateWithFlags(&s2, cudaStreamNonBlocking);
    cudaEvent_t evFork, evJoin;
    cudaEventCreateWithFlags(&evFork, cudaEventDisableTiming);
    cudaEventCreateWithFlags(&evJoin, cudaEventDisableTiming);

    cudaEventRecord(evFork, 0);
    cudaStreamWaitEvent(s2, evFork, 0);

    // CSR chain (side stream): memset deg, count, assign(cursor:=rowstart), fill(absolute)
    cudaMemsetAsync(deg_ptr, 0, (size_t)n * sizeof(int), s2);
    cudaMemsetAsync(total_ptr, 0, sizeof(int), s2);
    count_deg_kernel<<<(e + 255) / 256, 256, 0, s2>>>(dst, e);
    assign_kernel<<<(n + 255) / 256, 256, 0, s2>>>(n);
    fill_csr_kernel<<<(e + 255) / 256, 256, 0, s2>>>(src, dst, e);
    cudaEventRecord(evJoin, s2);

    int nblk = (n + 127) / 128;
    gemm1_kernel<<<nblk, 256, SMEM1>>>(x, Wl1, Wr1, bl1, n);

    cudaStreamWaitEvent(0, evJoin, 0);
    combine1_kernel<<<(n * 32 + 255) / 256, 256>>>(n);
    gemm2_kernel<<<nblk, 256, SMEM2>>>(Wl2, Wr2, bl2, n);
    combine2_kernel<<<(n * 32 + 255) / 256, 256>>>(out, n);
}